// round 1
// baseline (speedup 1.0000x reference)
#include <cuda_runtime.h>
#include <stdint.h>

#define N_MAX 20000
#define DEG 32

// Scratch (static __device__ — no allocations allowed)
__device__ int    g_nbr[N_MAX * DEG];     // sorted neighbor ids per node
__device__ float4 g_quat[N_MAX * DEG];    // sorted edge quats per node
__device__ int    g_queue[N_MAX];         // BFS queue
__device__ int    g_parent[N_MAX];        // winning (sorted) edge index per claimed node

// Replicate XLA's acos lowering: acos(x) = 2*atan2(sqrt(1-x*x), 1+x), all f32 RN.
// err = 2 * degrees(acos(|w| clipped to [0,1]))
__device__ __forceinline__ float err_key(float w) {
    float x = fminf(fabsf(w), 1.0f);
    float t = __fsub_rn(1.0f, __fmul_rn(x, x));
    float s = __fsqrt_rn(t);
    float a = atan2f(s, __fadd_rn(1.0f, x));
    float acosv = __fmul_rn(2.0f, a);
    float deg   = __fmul_rn(acosv, 57.29577951308232f);  // degrees()
    return __fmul_rn(2.0f, deg);                          // 2 * degrees
}

// Kernel 1: per-node stable sort of the 32 out-edges by err (one warp per node),
// plus identity-init of the output quats.
__global__ void sort_init_kernel(const float* __restrict__ edge_attr,
                                 const int*   __restrict__ edge_index,
                                 const int*   __restrict__ start_ptr,
                                 float*       __restrict__ out,
                                 int N, int E, int base) {
    int gwarp = (blockIdx.x * blockDim.x + threadIdx.x) >> 5;
    int lane  = threadIdx.x & 31;
    if (gwarp >= N) return;

    int e = gwarp * DEG + lane;
    int v = edge_index[E + e];                 // dst row of edge_index [2,E]
    float4 q = reinterpret_cast<const float4*>(edge_attr)[e];

    float err = err_key(q.x);                  // component 0 = w
    // err >= 0 -> float bits are order-preserving. Stable tie-break via lane.
    unsigned long long key =
        ((unsigned long long)__float_as_uint(err) << 6) | (unsigned)lane;

    // Bitonic sort of 32 keys in a warp, ascending.
    #pragma unroll
    for (int k = 2; k <= 32; k <<= 1) {
        #pragma unroll
        for (int j = k >> 1; j > 0; j >>= 1) {
            unsigned long long o = __shfl_xor_sync(0xffffffffu, key, j);
            bool lower    = (lane & j) == 0;
            bool asc      = (lane & k) == 0;   // k==32 -> ascending everywhere
            bool keep_min = (lower == asc);
            bool swap     = keep_min ? (o < key) : (o > key);
            if (swap) key = o;
        }
    }

    int o = (int)(key & 63u);  // original lane of my sorted slot
    int    sv = __shfl_sync(0xffffffffu, v,   o);
    float4 sq;
    sq.x = __shfl_sync(0xffffffffu, q.x, o);
    sq.y = __shfl_sync(0xffffffffu, q.y, o);
    sq.z = __shfl_sync(0xffffffffu, q.z, o);
    sq.w = __shfl_sync(0xffffffffu, q.w, o);

    g_nbr[e]  = sv;
    g_quat[e] = sq;

    // Identity-init this node's output quat (d_out is poisoned).
    if (lane < 4)
        out[base + gwarp * 4 + lane] = (lane == 0) ? 1.0f : 0.0f;
    if (gwarp == 0 && lane == 0) {
        int s = start_ptr ? start_ptr[0] : 0;
        for (int i = 0; i < base; i++) out[i] = (float)s;
    }
}

// Kernel 2: single-block. Warp 0 runs the sequential claim/BFS (exact reference
// order semantics); warps 1..7 prefetch upcoming queue entries' neighbor lines.
// Then the whole block does level-parallel quaternion propagation.
__global__ __launch_bounds__(256, 1)
void bfs_kernel(const int* __restrict__ start_ptr,
                float* __restrict__ out, int N, int base) {
    __shared__ unsigned char visited[N_MAX];
    __shared__ int s_level_end[64];
    __shared__ int s_nlev;
    __shared__ volatile int s_head, s_tail, s_done;

    int tid  = threadIdx.x;
    int lane = tid & 31;
    int wid  = tid >> 5;

    for (int i = tid; i < N; i += blockDim.x) visited[i] = 0;
    if (tid == 0) { s_head = 0; s_tail = 1; s_done = 0; }
    __syncthreads();

    int start = start_ptr ? start_ptr[0] : 0;
    if (start < 0 || start >= N) start = 0;
    if (tid == 0) { visited[start] = 1; g_queue[0] = start; }
    __syncthreads();

    if (wid == 0) {
        // ---- Sequential claim loop (exact reference ordering) ----
        int head = 0, tail = 1;
        int cur_end = 1, nlev = 1;
        if (lane == 0) s_level_end[0] = 1;
        while (head < tail) {
            if (head == cur_end) {              // new BFS level begins
                cur_end = tail;
                if (lane == 0) s_level_end[nlev] = tail;
                nlev++;
            }
            int u = g_queue[head];
            int e = u * DEG + lane;
            int v = g_nbr[e];
            unsigned vis   = visited[v];
            unsigned mmask = __match_any_sync(0xffffffffu, v);
            unsigned lt    = (1u << lane) - 1u;
            bool leader = (mmask & lt) == 0;    // lowest lane with this target
            bool take   = leader && (vis == 0);
            unsigned tm = __ballot_sync(0xffffffffu, take);
            int rank = __popc(tm & lt);
            if (take) {
                visited[v] = 1;
                g_queue[tail + rank] = v;
                g_parent[v] = e;
            }
            tail += __popc(tm);
            head++;
            if (lane == 0) { s_head = head; s_tail = tail; }
            __syncwarp();
        }
        if (lane == 0) {
            s_level_end[nlev] = tail;   // harmless sentinel
            s_nlev = nlev;
            s_done = 1;
        }
    } else {
        // ---- Prefetch helpers: pull upcoming neighbor lines into L1 ----
        int last = -1;
        while (s_done == 0) {
            int h = s_head, t = s_tail;
            int target = h + wid;               // lookahead = warp id (1..7)
            if (target < t && target < N && target != last) {
                last = target;
                int u = g_queue[target];
                if (u >= 0 && u < N) {
                    int vv = g_nbr[u * DEG + lane];
                    if (vv == -123456789) g_parent[0] = vv;  // keep load alive
                }
            } else {
                __nanosleep(40);
            }
        }
    }
    __syncthreads();

    // ---- Level-parallel quaternion propagation ----
    int nlev = s_nlev;
    for (int lev = 1; lev < nlev; lev++) {
        int sbeg = s_level_end[lev - 1];
        int send = s_level_end[lev];
        for (int pos = sbeg + tid; pos < send; pos += blockDim.x) {
            int v = g_queue[pos];
            int e = g_parent[v];
            int u = e / DEG;
            float4 q = g_quat[e];
            float uw = out[base + 4 * u + 0];
            float ux = out[base + 4 * u + 1];
            float uy = out[base + 4 * u + 2];
            float uz = out[base + 4 * u + 3];
            // qmul(inv(q), qu):  inv(q) = (w, -x, -y, -z)
            float w1 = q.x, x1 = -q.y, y1 = -q.z, z1 = -q.w;
            float rw = w1 * uw - x1 * ux - y1 * uy - z1 * uz;
            float rx = w1 * ux + x1 * uw + y1 * uz - z1 * uy;
            float ry = w1 * uy - x1 * uz + y1 * uw + z1 * ux;
            float rz = w1 * uz + x1 * uy - y1 * ux + z1 * uw;
            out[base + 4 * v + 0] = rw;
            out[base + 4 * v + 1] = rx;
            out[base + 4 * v + 2] = ry;
            out[base + 4 * v + 3] = rz;
        }
        __syncthreads();
    }
}

extern "C" void kernel_launch(void* const* d_in, const int* in_sizes, int n_in,
                              void* d_out, int out_size) {
    const float* edge_attr = (const float*)d_in[0];
    const int*   edge_index = (const int*)d_in[1];
    const int*   start_ptr  = (n_in >= 3) ? (const int*)d_in[2] : nullptr;
    float* out = (float*)d_out;

    int E = in_sizes[0] / 4;     // edge_attr is [E,4]
    int N = E / DEG;
    if (N > N_MAX) N = N_MAX;
    int base = out_size - N * 4; // 0 if output is just node_quat, 1 if start_node leads
    if (base < 0) base = 0;

    int threads = 256;
    int blocks = (N * 32 + threads - 1) / threads;
    sort_init_kernel<<<blocks, threads>>>(edge_attr, edge_index, start_ptr, out, N, E, base);
    bfs_kernel<<<1, 256>>>(start_ptr, out, N, base);
}

// round 2
// speedup vs baseline: 9.6982x; 9.6982x over previous
#include <cuda_runtime.h>
#include <stdint.h>

#define N_MAX 20000
#define DEG 32
#define NBW ((N_MAX + 31) / 32)   // visited bitmap words (625)

// Scratch (static __device__ — no allocations allowed)
__device__ int      g_nbr[N_MAX * DEG];    // sorted neighbor ids per node
__device__ float4   g_quat[N_MAX * DEG];   // sorted edge quats per node
__device__ int      g_queue[N_MAX];        // BFS queue (claim order)
__device__ int      g_parent[N_MAX];       // winning sorted-edge index per claimed node
__device__ unsigned g_claim[N_MAX];        // per-node min claim key (reinit each run)
__device__ int      g_levels[N_MAX + 2];   // level boundaries in queue

// Replicate XLA's acos lowering: acos(x) = 2*atan2(sqrt(1-x*x), 1+x), all f32 RN.
// err = 2 * degrees(acos(|w| clipped to [0,1]))
__device__ __forceinline__ float err_key(float w) {
    float x = fminf(fabsf(w), 1.0f);
    float t = __fsub_rn(1.0f, __fmul_rn(x, x));
    float s = __fsqrt_rn(t);
    float a = atan2f(s, __fadd_rn(1.0f, x));
    float acosv = __fmul_rn(2.0f, a);
    float deg   = __fmul_rn(acosv, 57.29577951308232f);
    return __fmul_rn(2.0f, deg);
}

// Kernel 1: per-node stable sort of the 32 out-edges by err (one warp per node),
// identity-init of output quats, and per-run reinit of g_claim.
__global__ void sort_init_kernel(const float* __restrict__ edge_attr,
                                 const int*   __restrict__ edge_index,
                                 const int*   __restrict__ start_ptr,
                                 float*       __restrict__ out,
                                 int N, int E, int base) {
    int gwarp = (blockIdx.x * blockDim.x + threadIdx.x) >> 5;
    int lane  = threadIdx.x & 31;
    if (gwarp >= N) return;

    int e = gwarp * DEG + lane;
    int v = edge_index[E + e];                 // dst row of edge_index [2,E]
    float4 q = reinterpret_cast<const float4*>(edge_attr)[e];

    float err = err_key(q.x);                  // component 0 = w
    // err >= 0 -> float bits are order-preserving. Stable tie-break via lane.
    unsigned long long key =
        ((unsigned long long)__float_as_uint(err) << 6) | (unsigned)lane;

    #pragma unroll
    for (int k = 2; k <= 32; k <<= 1) {
        #pragma unroll
        for (int j = k >> 1; j > 0; j >>= 1) {
            unsigned long long o = __shfl_xor_sync(0xffffffffu, key, j);
            bool lower    = (lane & j) == 0;
            bool asc      = (lane & k) == 0;
            bool keep_min = (lower == asc);
            bool swap     = keep_min ? (o < key) : (o > key);
            if (swap) key = o;
        }
    }

    int o = (int)(key & 63u);
    int    sv = __shfl_sync(0xffffffffu, v,   o);
    float4 sq;
    sq.x = __shfl_sync(0xffffffffu, q.x, o);
    sq.y = __shfl_sync(0xffffffffu, q.y, o);
    sq.z = __shfl_sync(0xffffffffu, q.z, o);
    sq.w = __shfl_sync(0xffffffffu, q.w, o);

    g_nbr[e]  = sv;
    g_quat[e] = sq;

    if (lane == 0) g_claim[gwarp] = 0xffffffffu;   // reinit per run
    if (lane < 4)
        out[base + gwarp * 4 + lane] = (lane == 0) ? 1.0f : 0.0f;
    if (gwarp == 0 && lane == 0) {
        int s = start_ptr ? start_ptr[0] : 0;
        for (int i = 0; i < base; i++) out[i] = (float)s;
    }
}

// Kernel 2: single 1024-thread block, level-synchronous BFS reproducing the
// reference's sequential claim order exactly:
//   - a node v is claimed by the min key (queue_pos<<5 | sorted_lane) among
//     frontier edges targeting it (absolute queue_pos makes stale claims lose)
//   - next-level queue order = ascending winner key (stable block compaction)
// Then level-parallel quaternion propagation along the parent tree.
__global__ __launch_bounds__(1024, 1)
void bfs_kernel(const int* __restrict__ start_ptr,
                float* __restrict__ out, int N, int base) {
    __shared__ unsigned s_vis[NBW + 7];
    __shared__ int s_cnt[32];
    __shared__ int s_off[32];

    const int tid  = threadIdx.x;
    const int lane = tid & 31;
    const int wid  = tid >> 5;
    const unsigned FULL = 0xffffffffu;
    const unsigned lt   = (1u << lane) - 1u;

    for (int i = tid; i < NBW; i += blockDim.x) s_vis[i] = 0u;
    __syncthreads();

    int start = start_ptr ? start_ptr[0] : 0;
    if (start < 0 || start >= N) start = 0;
    if (tid == 0) {
        atomicOr(&s_vis[start >> 5], 1u << (start & 31));
        g_queue[0]  = start;
        g_levels[0] = 0;
        g_levels[1] = 1;
    }
    __syncthreads();

    int lev_beg = 0, lev_end = 1, tail = 1, lev = 0;

    while (lev_beg < lev_end) {
        // ---- Pass 1: claims (predicated global atomicMin) ----
        for (int p = lev_beg + wid; p < lev_end; p += 32) {
            int u = g_queue[p];
            int v = g_nbr[(u << 5) + lane];
            bool unv = ((s_vis[v >> 5] >> (v & 31)) & 1u) == 0u;
            if (unv) atomicMin(&g_claim[v], (unsigned)((p << 5) | lane));
        }
        __syncthreads();

        // ---- Pass 2: winner re-check + stable ordered compaction ----
        // Tile = 128 frontier entries (4 per warp, ascending p within warp).
        for (int tb = lev_beg; tb < lev_end; tb += 128) {
            unsigned m_sub[4];
            int v_sub[4], e_sub[4];
            int mycnt = 0;
            #pragma unroll
            for (int i = 0; i < 4; i++) {
                int p = tb + (wid << 2) + i;
                bool win = false; int v = -1, e = 0;
                if (p < lev_end) {
                    int u = g_queue[p];
                    v = g_nbr[(u << 5) + lane];
                    bool unv = ((s_vis[v >> 5] >> (v & 31)) & 1u) == 0u;
                    unsigned c = unv ? g_claim[v] : 0xffffffffu;
                    win = (c == (unsigned)((p << 5) | lane));
                    e = (u << 5) | lane;
                }
                m_sub[i] = __ballot_sync(FULL, win);
                v_sub[i] = v; e_sub[i] = e;
                mycnt += __popc(m_sub[i]);
            }
            if (lane == 0) s_cnt[wid] = mycnt;
            __syncthreads();
            if (wid == 0) {
                int c = s_cnt[lane];
                int x = c;
                #pragma unroll
                for (int d = 1; d < 32; d <<= 1) {
                    int y = __shfl_up_sync(FULL, x, d);
                    if (lane >= d) x += y;
                }
                s_off[lane] = x - c;   // exclusive
            }
            __syncthreads();
            int off = tail + s_off[wid];
            #pragma unroll
            for (int i = 0; i < 4; i++) {
                bool win = (m_sub[i] >> lane) & 1u;
                if (win) {
                    int pos = off + __popc(m_sub[i] & lt);
                    int v = v_sub[i];
                    g_queue[pos]  = v;
                    g_parent[v]   = e_sub[i];
                    atomicOr(&s_vis[v >> 5], 1u << (v & 31));
                }
                off += __popc(m_sub[i]);
            }
            int tile_total = s_off[31] + s_cnt[31];
            __syncthreads();   // protect s_cnt/s_off before next tile
            tail += tile_total;
        }

        if (tid == 0) g_levels[lev + 2] = tail;
        lev++;
        lev_beg = lev_end;
        lev_end = tail;
        __syncthreads();       // make g_levels + queue writes visible
    }

    int nlevels = lev;         // levels 0..nlevels-1 contain nodes

    // ---- Level-parallel quaternion propagation ----
    for (int l = 1; l < nlevels; l++) {
        int sbeg = g_levels[l];
        int send = g_levels[l + 1];
        for (int pos = sbeg + tid; pos < send; pos += blockDim.x) {
            int v = g_queue[pos];
            int e = g_parent[v];
            int u = e >> 5;
            float4 q = g_quat[e];
            float uw = out[base + 4 * u + 0];
            float ux = out[base + 4 * u + 1];
            float uy = out[base + 4 * u + 2];
            float uz = out[base + 4 * u + 3];
            // qmul(inv(q), qu):  inv(q) = (w, -x, -y, -z)
            float w1 = q.x, x1 = -q.y, y1 = -q.z, z1 = -q.w;
            float rw = w1 * uw - x1 * ux - y1 * uy - z1 * uz;
            float rx = w1 * ux + x1 * uw + y1 * uz - z1 * uy;
            float ry = w1 * uy - x1 * uz + y1 * uw + z1 * ux;
            float rz = w1 * uz + x1 * uy - y1 * ux + z1 * uw;
            out[base + 4 * v + 0] = rw;
            out[base + 4 * v + 1] = rx;
            out[base + 4 * v + 2] = ry;
            out[base + 4 * v + 3] = rz;
        }
        __syncthreads();
    }
}

extern "C" void kernel_launch(void* const* d_in, const int* in_sizes, int n_in,
                              void* d_out, int out_size) {
    const float* edge_attr  = (const float*)d_in[0];
    const int*   edge_index = (const int*)d_in[1];
    const int*   start_ptr  = (n_in >= 3) ? (const int*)d_in[2] : nullptr;
    float* out = (float*)d_out;

    int E = in_sizes[0] / 4;     // edge_attr is [E,4]
    int N = E / DEG;
    if (N > N_MAX) N = N_MAX;
    int base = out_size - N * 4;
    if (base < 0) base = 0;

    int threads = 256;
    int blocks = (N * 32 + threads - 1) / threads;
    sort_init_kernel<<<blocks, threads>>>(edge_attr, edge_index, start_ptr, out, N, E, base);
    bfs_kernel<<<1, 1024>>>(start_ptr, out, N, base);
}

// round 3
// speedup vs baseline: 42.2731x; 4.3589x over previous
#include <cuda_runtime.h>
#include <stdint.h>

#define N_MAX   20000
#define DEG     32
#define NBW     ((N_MAX + 31) / 32)   // visited bitmap words (625)
#define NBLOCKS 112
#define NTHREADS 512
#define MAX_CHUNK 256                  // >= ceil(N_MAX/NBLOCKS) = 179
#define MAX_LEV  60

// Scratch (static __device__ — no allocations allowed)
__device__ int      g_nbr[N_MAX * DEG];    // sorted neighbor ids per node
__device__ float4   g_quat[N_MAX * DEG];   // sorted edge quats per node
__device__ int      g_queue[N_MAX];        // BFS queue (claim order)
__device__ int      g_parent[N_MAX];       // winning sorted-edge index per claimed node
__device__ unsigned g_claim[N_MAX];        // per-node min claim key (reinit each run)
__device__ unsigned g_vis[NBW];            // visited bitmap (reinit each run)
__device__ int      g_levels[MAX_LEV + 4]; // level boundaries in queue
__device__ int      g_blkcnt[NBLOCKS];     // per-block winner counts (per level)

// software grid barrier state (self-restoring across graph replays)
__device__ unsigned          g_bar_cnt = 0;
__device__ volatile unsigned g_bar_gen = 0;

__device__ __forceinline__ void grid_barrier() {
    __syncthreads();
    if (threadIdx.x == 0) {
        unsigned gen = g_bar_gen;
        __threadfence();
        if (atomicAdd(&g_bar_cnt, 1u) == (unsigned)(NBLOCKS - 1)) {
            g_bar_cnt = 0;
            __threadfence();
            g_bar_gen = gen + 1;
        } else {
            while (g_bar_gen == gen) __nanosleep(32);
        }
        __threadfence();
    }
    __syncthreads();
}

// Replicate XLA's acos lowering: acos(x) = 2*atan2(sqrt(1-x*x), 1+x), all f32 RN.
__device__ __forceinline__ float err_key(float w) {
    float x = fminf(fabsf(w), 1.0f);
    float t = __fsub_rn(1.0f, __fmul_rn(x, x));
    float s = __fsqrt_rn(t);
    float a = atan2f(s, __fadd_rn(1.0f, x));
    float acosv = __fmul_rn(2.0f, a);
    float deg   = __fmul_rn(acosv, 57.29577951308232f);
    return __fmul_rn(2.0f, deg);
}

// Kernel 1: per-node stable sort of 32 out-edges (one warp per node),
// identity-init of output, per-run reinit of g_claim and g_vis.
__global__ void sort_init_kernel(const float* __restrict__ edge_attr,
                                 const int*   __restrict__ edge_index,
                                 const int*   __restrict__ start_ptr,
                                 float*       __restrict__ out,
                                 int N, int E, int base) {
    int gt    = blockIdx.x * blockDim.x + threadIdx.x;
    int gwarp = gt >> 5;
    int lane  = threadIdx.x & 31;

    if (gt < NBW) g_vis[gt] = 0u;              // reinit per run
    if (gwarp >= N) return;

    int e = gwarp * DEG + lane;
    int v = edge_index[E + e];                 // dst row of edge_index [2,E]
    float4 q = reinterpret_cast<const float4*>(edge_attr)[e];

    float err = err_key(q.x);                  // component 0 = w
    unsigned long long key =
        ((unsigned long long)__float_as_uint(err) << 6) | (unsigned)lane;

    #pragma unroll
    for (int k = 2; k <= 32; k <<= 1) {
        #pragma unroll
        for (int j = k >> 1; j > 0; j >>= 1) {
            unsigned long long o = __shfl_xor_sync(0xffffffffu, key, j);
            bool lower    = (lane & j) == 0;
            bool asc      = (lane & k) == 0;
            bool keep_min = (lower == asc);
            bool swap     = keep_min ? (o < key) : (o > key);
            if (swap) key = o;
        }
    }

    int o = (int)(key & 63u);
    int    sv = __shfl_sync(0xffffffffu, v,   o);
    float4 sq;
    sq.x = __shfl_sync(0xffffffffu, q.x, o);
    sq.y = __shfl_sync(0xffffffffu, q.y, o);
    sq.z = __shfl_sync(0xffffffffu, q.z, o);
    sq.w = __shfl_sync(0xffffffffu, q.w, o);

    g_nbr[e]  = sv;
    g_quat[e] = sq;

    if (lane == 0) g_claim[gwarp] = 0xffffffffu;   // reinit per run
    if (lane < 4)
        out[base + gwarp * 4 + lane] = (lane == 0) ? 1.0f : 0.0f;
    if (gwarp == 0 && lane == 0) {
        int s = start_ptr ? start_ptr[0] : 0;
        for (int i = 0; i < base; i++) out[i] = (float)s;
    }
}

// Kernel 2: persistent whole-chip level-synchronous BFS (exact reference order):
//   node v claimed by min key (queue_pos<<5 | sorted_lane) over frontier edges;
//   next-level queue = ascending winner key (stable cross-block compaction).
// Then level-parallel quaternion propagation.
// All cross-block-written data is read with __ldcg (L1 not coherent across SMs).
__global__ __launch_bounds__(NTHREADS, 1)
void bfs_kernel(const int* __restrict__ start_ptr,
                float* __restrict__ out, int N, int base) {
    __shared__ unsigned s_mask[MAX_CHUNK];
    __shared__ int      s_val[MAX_CHUNK];
    __shared__ int      s_u[MAX_CHUNK];
    __shared__ int      s_before, s_total;

    const int tid  = threadIdx.x;
    const int lane = tid & 31;
    const int wid  = tid >> 5;
    const int bid  = blockIdx.x;
    const int nwb  = NTHREADS / 32;                 // warps per block
    const int gwarp   = bid * nwb + wid;
    const int gwstride = NBLOCKS * nwb;
    const unsigned FULL = 0xffffffffu;
    const unsigned lt   = (1u << lane) - 1u;

    if (bid == 0 && tid == 0) {
        int start = start_ptr ? __ldcg(start_ptr) : 0;
        if (start < 0 || start >= N) start = 0;
        g_queue[0]  = start;
        atomicOr(&g_vis[start >> 5], 1u << (start & 31));
        g_levels[0] = 0;
        g_levels[1] = 1;
    }
    grid_barrier();

    int lev_beg = 0, lev_end = 1, tail = 1, lev = 0;

    while (lev_beg < lev_end && lev < MAX_LEV) {
        // ---- Phase A: claims (whole grid, warp per frontier entry) ----
        for (int p = lev_beg + gwarp; p < lev_end; p += gwstride) {
            int u = __ldcg(&g_queue[p]);
            int v = g_nbr[(u << 5) + lane];
            bool unv = ((__ldcg(&g_vis[v >> 5]) >> (v & 31)) & 1u) == 0u;
            if (unv) atomicMin(&g_claim[v], (unsigned)((p << 5) | lane));
        }
        grid_barrier();

        // ---- Phase B: winner masks + per-block count (contiguous chunks) ----
        int len   = lev_end - lev_beg;
        int chunk = (len + NBLOCKS - 1) / NBLOCKS;       // <= MAX_CHUNK
        int cbeg  = lev_beg + bid * chunk;
        int cend  = cbeg + chunk; if (cend > lev_end) cend = lev_end;
        int clen  = cend - cbeg;  if (clen < 0) clen = 0;

        for (int ei = wid; ei < clen; ei += nwb) {
            int p = cbeg + ei;
            int u = __ldcg(&g_queue[p]);
            int v = g_nbr[(u << 5) + lane];
            bool unv = ((__ldcg(&g_vis[v >> 5]) >> (v & 31)) & 1u) == 0u;
            bool win = unv && (__ldcg(&g_claim[v]) == (unsigned)((p << 5) | lane));
            unsigned m = __ballot_sync(FULL, win);
            if (lane == 0) { s_mask[ei] = m; s_u[ei] = u; }
        }
        __syncthreads();

        // inclusive Hillis-Steele scan of popc(mask) over the chunk
        int myc = (tid < clen) ? __popc(s_mask[tid]) : 0;
        if (tid < MAX_CHUNK) s_val[tid] = myc;
        __syncthreads();
        #pragma unroll
        for (int d = 1; d < MAX_CHUNK; d <<= 1) {
            int add = 0;
            if (tid < MAX_CHUNK && tid >= d) add = s_val[tid - d];
            __syncthreads();
            if (tid < MAX_CHUNK) s_val[tid] += add;
            __syncthreads();
        }
        if (tid == 0) g_blkcnt[bid] = (clen > 0) ? s_val[clen - 1] : 0;
        grid_barrier();

        // ---- Phase C: block offset via scan of counts, then ordered writes ----
        if (wid == 0) {
            int acc_b = 0, acc_t = 0;
            for (int j = lane; j < NBLOCKS; j += 32) {
                int c = __ldcg(&g_blkcnt[j]);
                acc_t += c;
                if (j < bid) acc_b += c;
            }
            #pragma unroll
            for (int d = 16; d > 0; d >>= 1) {
                acc_b += __shfl_xor_sync(FULL, acc_b, d);
                acc_t += __shfl_xor_sync(FULL, acc_t, d);
            }
            if (lane == 0) { s_before = acc_b; s_total = acc_t; }
        }
        __syncthreads();

        int blkoff = tail + s_before;
        for (int ei = wid; ei < clen; ei += nwb) {
            unsigned m = s_mask[ei];
            if (!m) continue;
            int u = s_u[ei];
            int eoff = s_val[ei] - __popc(m);           // exclusive within chunk
            if ((m >> lane) & 1u) {
                int v = g_nbr[(u << 5) + lane];
                int pos = blkoff + eoff + __popc(m & lt);
                g_queue[pos]  = v;
                g_parent[v]   = (u << 5) | lane;
                atomicOr(&g_vis[v >> 5], 1u << (v & 31));
            }
        }

        int new_tail = tail + s_total;
        if (bid == 0 && tid == 0) g_levels[lev + 2] = new_tail;
        tail = new_tail; lev++;
        lev_beg = lev_end; lev_end = tail;
        grid_barrier();
    }

    // ---- Level-parallel quaternion propagation (whole grid) ----
    int nlev = lev;
    const int gtid    = bid * NTHREADS + tid;
    const int gstride = NBLOCKS * NTHREADS;
    for (int l = 1; l < nlev; l++) {
        int sbeg = __ldcg(&g_levels[l]);
        int send = __ldcg(&g_levels[l + 1]);
        for (int pos = sbeg + gtid; pos < send; pos += gstride) {
            int v = __ldcg(&g_queue[pos]);
            int e = __ldcg(&g_parent[v]);
            int u = e >> 5;
            float4 q = g_quat[e];
            float uw = __ldcg(&out[base + 4 * u + 0]);
            float ux = __ldcg(&out[base + 4 * u + 1]);
            float uy = __ldcg(&out[base + 4 * u + 2]);
            float uz = __ldcg(&out[base + 4 * u + 3]);
            // qmul(inv(q), qu):  inv(q) = (w, -x, -y, -z)
            float w1 = q.x, x1 = -q.y, y1 = -q.z, z1 = -q.w;
            float rw = w1 * uw - x1 * ux - y1 * uy - z1 * uz;
            float rx = w1 * ux + x1 * uw + y1 * uz - z1 * uy;
            float ry = w1 * uy - x1 * uz + y1 * uw + z1 * ux;
            float rz = w1 * uz + x1 * uy - y1 * ux + z1 * uw;
            out[base + 4 * v + 0] = rw;
            out[base + 4 * v + 1] = rx;
            out[base + 4 * v + 2] = ry;
            out[base + 4 * v + 3] = rz;
        }
        grid_barrier();
    }
}

extern "C" void kernel_launch(void* const* d_in, const int* in_sizes, int n_in,
                              void* d_out, int out_size) {
    const float* edge_attr  = (const float*)d_in[0];
    const int*   edge_index = (const int*)d_in[1];
    const int*   start_ptr  = (n_in >= 3) ? (const int*)d_in[2] : nullptr;
    float* out = (float*)d_out;

    int E = in_sizes[0] / 4;     // edge_attr is [E,4]
    int N = E / DEG;
    if (N > N_MAX) N = N_MAX;
    int base = out_size - N * 4;
    if (base < 0) base = 0;

    int threads = 256;
    int blocks = (N * 32 + threads - 1) / threads;
    sort_init_kernel<<<blocks, threads>>>(edge_attr, edge_index, start_ptr, out, N, E, base);
    bfs_kernel<<<NBLOCKS, NTHREADS>>>(start_ptr, out, N, base);
}

// round 4
// speedup vs baseline: 65.0964x; 1.5399x over previous
#include <cuda_runtime.h>
#include <stdint.h>

#define N_MAX     20000
#define DEG       32
#define NBW       ((N_MAX + 31) / 32)   // visited bitmap words (625)
#define NBLOCKS   112
#define NTHREADS  512
#define NWB       (NTHREADS / 32)       // 16 warps per block
#define CHUNK_CAP 192                   // >= ceil(N_MAX/NBLOCKS)=179 and >= FAST_MAX
#define FAST_MAX  128                   // small-level single-block fast path
#define MAX_LEV   60

// Scratch (static __device__ — no allocations allowed)
__device__ int      g_nbr[N_MAX * DEG];    // sorted neighbor ids per node
__device__ float4   g_quat[N_MAX * DEG];   // sorted edge quats per node
__device__ int      g_queue[N_MAX];        // BFS queue (claim order)
__device__ unsigned g_claim[N_MAX];        // per-node min claim key (reinit each run)
__device__ unsigned g_vis[NBW];            // visited bitmap (reinit each run)
__device__ int      g_levels[MAX_LEV + 4]; // level boundaries in queue
__device__ int      g_blkcnt[NBLOCKS];     // per-block winner counts (per level)

// software grid barrier (self-restoring across graph replays)
__device__ unsigned          g_bar_cnt = 0;
__device__ volatile unsigned g_bar_gen = 0;

__device__ __forceinline__ void grid_barrier() {
    __syncthreads();
    if (threadIdx.x == 0) {
        unsigned gen = g_bar_gen;
        __threadfence();
        if (atomicAdd(&g_bar_cnt, 1u) == (unsigned)(NBLOCKS - 1)) {
            g_bar_cnt = 0;
            __threadfence();
            g_bar_gen = gen + 1;
        } else {
            while (g_bar_gen == gen) __nanosleep(20);
        }
        __threadfence();
    }
    __syncthreads();
}

// Replicate XLA's acos lowering: acos(x) = 2*atan2(sqrt(1-x*x), 1+x), all f32 RN.
__device__ __forceinline__ float err_key(float w) {
    float x = fminf(fabsf(w), 1.0f);
    float t = __fsub_rn(1.0f, __fmul_rn(x, x));
    float s = __fsqrt_rn(t);
    float a = atan2f(s, __fadd_rn(1.0f, x));
    float acosv = __fmul_rn(2.0f, a);
    float deg   = __fmul_rn(acosv, 57.29577951308232f);
    return __fmul_rn(2.0f, deg);
}

// Kernel 1: per-node stable sort of 32 out-edges (one warp per node),
// identity-init of output, per-run reinit of g_claim and g_vis.
__global__ void sort_init_kernel(const float* __restrict__ edge_attr,
                                 const int*   __restrict__ edge_index,
                                 const int*   __restrict__ start_ptr,
                                 float*       __restrict__ out,
                                 int N, int E, int base) {
    int gt    = blockIdx.x * blockDim.x + threadIdx.x;
    int gwarp = gt >> 5;
    int lane  = threadIdx.x & 31;

    if (gt < NBW) g_vis[gt] = 0u;              // reinit per run
    if (gwarp >= N) return;

    int e = gwarp * DEG + lane;
    int v = edge_index[E + e];                 // dst row of edge_index [2,E]
    float4 q = reinterpret_cast<const float4*>(edge_attr)[e];

    float err = err_key(q.x);                  // component 0 = w
    unsigned long long key =
        ((unsigned long long)__float_as_uint(err) << 6) | (unsigned)lane;

    #pragma unroll
    for (int k = 2; k <= 32; k <<= 1) {
        #pragma unroll
        for (int j = k >> 1; j > 0; j >>= 1) {
            unsigned long long o = __shfl_xor_sync(0xffffffffu, key, j);
            bool lower    = (lane & j) == 0;
            bool asc      = (lane & k) == 0;
            bool keep_min = (lower == asc);
            bool swap     = keep_min ? (o < key) : (o > key);
            if (swap) key = o;
        }
    }

    int o = (int)(key & 63u);
    int    sv = __shfl_sync(0xffffffffu, v,   o);
    float4 sq;
    sq.x = __shfl_sync(0xffffffffu, q.x, o);
    sq.y = __shfl_sync(0xffffffffu, q.y, o);
    sq.z = __shfl_sync(0xffffffffu, q.z, o);
    sq.w = __shfl_sync(0xffffffffu, q.w, o);

    g_nbr[e]  = sv;
    g_quat[e] = sq;

    if (lane == 0) g_claim[gwarp] = 0xffffffffu;   // reinit per run
    if (lane < 4)
        out[base + gwarp * 4 + lane] = (lane == 0) ? 1.0f : 0.0f;
    if (gwarp == 0 && lane == 0) {
        int s = start_ptr ? start_ptr[0] : 0;
        for (int i = 0; i < base; i++) out[i] = (float)s;
    }
}

// Kernel 2: persistent whole-chip level-synchronous BFS, exact reference order.
// Node v claimed by min key (queue_pos<<5 | sorted_lane) over frontier edges;
// next-level queue = ascending winner key. Quaternion computed AT claim time
// (parent's quat final since previous level). Small levels: single-block path.
__global__ __launch_bounds__(NTHREADS, 1)
void bfs_kernel(const int* __restrict__ start_ptr,
                float* __restrict__ out, int N, int base) {
    __shared__ int      s_u[CHUNK_CAP];
    __shared__ unsigned s_unv[CHUNK_CAP];
    __shared__ unsigned s_win[CHUNK_CAP];
    __shared__ int      s_off[CHUNK_CAP];
    __shared__ int      s_wsum[NWB];
    __shared__ int      s_woff[NWB];
    __shared__ int      s_total, s_before;

    const int tid  = threadIdx.x;
    const int lane = tid & 31;
    const int wid  = tid >> 5;
    const int bid  = blockIdx.x;
    const unsigned FULL = 0xffffffffu;
    const unsigned lt   = (1u << lane) - 1u;

    if (bid == 0 && tid == 0) {
        int start = start_ptr ? __ldcg(start_ptr) : 0;
        if (start < 0 || start >= N) start = 0;
        g_queue[0]  = start;
        atomicOr(&g_vis[start >> 5], 1u << (start & 31));
        g_levels[0] = 0;
        g_levels[1] = 1;
    }
    grid_barrier();

    int lev_beg = 0, lev_end = 1, tail = 1, lev = 0;

    while (lev < MAX_LEV) {
        int len = lev_end - lev_beg;
        if (len <= 0) break;
        bool fast = (len <= FAST_MAX);

        int cbeg, clen;
        if (fast) { cbeg = lev_beg; clen = (bid == 0) ? len : 0; }
        else {
            int chunk = (len + NBLOCKS - 1) / NBLOCKS;     // <= CHUNK_CAP
            cbeg = lev_beg + bid * chunk;
            int cend = cbeg + chunk; if (cend > lev_end) cend = lev_end;
            clen = cend - cbeg; if (clen < 0) clen = 0;
        }

        // ---- Phase A: claims (chunked; cache u + unvisited ballot in smem) ----
        for (int ei = wid; ei < clen; ei += NWB) {
            int p = cbeg + ei;
            int u = __ldcg(&g_queue[p]);
            int v = g_nbr[(u << 5) + lane];
            bool unv = ((__ldcg(&g_vis[v >> 5]) >> (v & 31)) & 1u) == 0u;
            if (unv) atomicMin(&g_claim[v], (unsigned)((p << 5) | lane));
            unsigned m = __ballot_sync(FULL, unv);
            if (lane == 0) { s_u[ei] = u; s_unv[ei] = m; }
        }
        if (fast) { if (bid == 0) __syncthreads(); }
        else grid_barrier();

        // ---- Phase B: winner masks (reuse cached u / unv; g_nbr is L1-hot) ----
        for (int ei = wid; ei < clen; ei += NWB) {
            int p = cbeg + ei;
            int u = s_u[ei];
            bool cand = (s_unv[ei] >> lane) & 1u;
            bool win = false;
            if (cand) {
                int v = g_nbr[(u << 5) + lane];
                win = (__ldcg(&g_claim[v]) == (unsigned)((p << 5) | lane));
            }
            unsigned m = __ballot_sync(FULL, win);
            if (lane == 0) s_win[ei] = m;
        }
        if (!fast || bid == 0) {
            __syncthreads();
            // exclusive scan of popc(s_win) over clen entries (warp-shuffle)
            int c = (tid < clen) ? __popc(s_win[tid]) : 0;
            int x = c;
            #pragma unroll
            for (int d = 1; d < 32; d <<= 1) {
                int y = __shfl_up_sync(FULL, x, d);
                if (lane >= d) x += y;
            }
            if (lane == 31) s_wsum[wid] = x;
            __syncthreads();
            if (wid == 0 && lane < NWB) {
                int w = s_wsum[lane];
                int xx = w;
                #pragma unroll
                for (int d = 1; d < NWB; d <<= 1) {
                    int y = __shfl_up_sync(0x0000ffffu, xx, d);
                    if (lane >= d) xx += y;
                }
                s_woff[lane] = xx - w;
                if (lane == NWB - 1) s_total = xx;
            }
            __syncthreads();
            if (tid < clen) s_off[tid] = x - c + s_woff[wid];
            __syncthreads();
        }

        int blkoff;
        if (fast) {
            blkoff = tail;
        } else {
            if (tid == 0) g_blkcnt[bid] = s_total;
            grid_barrier();
            if (wid == 0) {
                int acc_b = 0, acc_t = 0;
                for (int j = lane; j < NBLOCKS; j += 32) {
                    int cc = __ldcg(&g_blkcnt[j]);
                    acc_t += cc;
                    if (j < bid) acc_b += cc;
                }
                #pragma unroll
                for (int d = 16; d > 0; d >>= 1) {
                    acc_b += __shfl_xor_sync(FULL, acc_b, d);
                    acc_t += __shfl_xor_sync(FULL, acc_t, d);
                }
                if (lane == 0) { s_before = acc_b; s_total = acc_t; }
            }
            __syncthreads();
            blkoff = tail + s_before;
        }

        // ---- Phase C: ordered queue writes + quat computation at claim ----
        for (int ei = wid; ei < clen; ei += NWB) {
            unsigned m = s_win[ei];
            if (m == 0u) continue;
            int u    = s_u[ei];
            int eoff = s_off[ei];
            if ((m >> lane) & 1u) {
                int e = (u << 5) + lane;
                int v = g_nbr[e];
                int pos = blkoff + eoff + __popc(m & lt);
                g_queue[pos] = v;
                atomicOr(&g_vis[v >> 5], 1u << (v & 31));
                float4 q = g_quat[e];
                float uw = __ldcg(&out[base + 4 * u + 0]);
                float ux = __ldcg(&out[base + 4 * u + 1]);
                float uy = __ldcg(&out[base + 4 * u + 2]);
                float uz = __ldcg(&out[base + 4 * u + 3]);
                // qmul(inv(q), qu):  inv(q) = (w, -x, -y, -z)
                float w1 = q.x, x1 = -q.y, y1 = -q.z, z1 = -q.w;
                float rw = w1 * uw - x1 * ux - y1 * uy - z1 * uz;
                float rx = w1 * ux + x1 * uw + y1 * uz - z1 * uy;
                float ry = w1 * uy - x1 * uz + y1 * uw + z1 * ux;
                float rz = w1 * uz + x1 * uy - y1 * ux + z1 * uw;
                __stcg(&out[base + 4 * v + 0], rw);
                __stcg(&out[base + 4 * v + 1], rx);
                __stcg(&out[base + 4 * v + 2], ry);
                __stcg(&out[base + 4 * v + 3], rz);
            }
        }

        if ((fast && bid == 0 && tid == 0) || (!fast && bid == 0 && tid == 0))
            g_levels[lev + 2] = tail + s_total;
        grid_barrier();

        lev++;
        lev_beg = lev_end;
        lev_end = __ldcg(&g_levels[lev + 1]);
        tail    = lev_end;
    }
}

extern "C" void kernel_launch(void* const* d_in, const int* in_sizes, int n_in,
                              void* d_out, int out_size) {
    const float* edge_attr  = (const float*)d_in[0];
    const int*   edge_index = (const int*)d_in[1];
    const int*   start_ptr  = (n_in >= 3) ? (const int*)d_in[2] : nullptr;
    float* out = (float*)d_out;

    int E = in_sizes[0] / 4;     // edge_attr is [E,4]
    int N = E / DEG;
    if (N > N_MAX) N = N_MAX;
    int base = out_size - N * 4;
    if (base < 0) base = 0;

    int threads = 256;
    int blocks = (N * 32 + threads - 1) / threads;
    sort_init_kernel<<<blocks, threads>>>(edge_attr, edge_index, start_ptr, out, N, E, base);
    bfs_kernel<<<NBLOCKS, NTHREADS>>>(start_ptr, out, N, base);
}

// round 5
// speedup vs baseline: 66.4335x; 1.0205x over previous
#include <cuda_runtime.h>
#include <stdint.h>

#define N_MAX     20000
#define DEG       32
#define NBLOCKS   112
#define NTHREADS  512
#define NWB       (NTHREADS / 32)       // 16 warps per block
#define CHUNK_CAP 192                   // >= ceil(N_MAX/NBLOCKS)=179, >= FAST_MAX
#define FAST_MAX  128                   // small-level single-block fast path
#define MAX_LEV   60

// Scratch (static __device__ — no allocations allowed)
__device__ int      g_nbr[N_MAX * DEG];     // sorted neighbor ids per node
__device__ float4   g_quat[N_MAX * DEG];    // sorted edge quats per node
__device__ float4   g_nq[N_MAX];            // node quaternions (aligned state)
__device__ int      g_queue[N_MAX];         // BFS queue (claim order)
__device__ unsigned g_claim[N_MAX];         // per-node min claim key (reinit per run)
__device__ int      g_levels[MAX_LEV + 4];  // level boundaries
__device__ unsigned long long g_cnt_tag[NBLOCKS];  // (tag<<32)|count publish slots

// hierarchical grid barrier (monotone counters — no reset races)
__device__ unsigned          g_bar_sub[4];
__device__ unsigned          g_bar_root;
__device__ volatile unsigned g_bar_gen;

__device__ __forceinline__ void grid_barrier() {
    __syncthreads();
    if (threadIdx.x == 0) {
        unsigned gen = g_bar_gen;
        __threadfence();
        int s = blockIdx.x & 3;
        unsigned my = atomicAdd(&g_bar_sub[s], 1u) + 1u;
        if ((my % (NBLOCKS / 4)) == 0u) {
            unsigned r = atomicAdd(&g_bar_root, 1u) + 1u;
            if ((r & 3u) == 0u) {
                __threadfence();
                g_bar_gen = gen + 1u;
            }
        }
        while (g_bar_gen == gen) __nanosleep(20);
        __threadfence();
    }
    __syncthreads();
}

// Replicate XLA's acos lowering: acos(x)=2*atan2(sqrt(1-x*x),1+x), all f32 RN.
__device__ __forceinline__ float err_key(float w) {
    float x = fminf(fabsf(w), 1.0f);
    float t = __fsub_rn(1.0f, __fmul_rn(x, x));
    float s = __fsqrt_rn(t);
    float a = atan2f(s, __fadd_rn(1.0f, x));
    float acosv = __fmul_rn(2.0f, a);
    float deg   = __fmul_rn(acosv, 57.29577951308232f);
    return __fmul_rn(2.0f, deg);
}

// Single persistent kernel: sort phase -> grid barrier -> level-synchronous BFS
// with claim-at-min-key semantics (exact reference order). No visited bitmap:
// claim keys are monotone across levels, so equality testing suffices
// (start node guarded explicitly). Quats computed at claim time.
__global__ __launch_bounds__(NTHREADS, 1)
void spt_kernel(const float* __restrict__ edge_attr,
                const int*   __restrict__ edge_index,
                const int*   __restrict__ start_ptr,
                float* __restrict__ out, int N, int E, int base) {
    __shared__ int      s_u[CHUNK_CAP];
    __shared__ unsigned s_win[CHUNK_CAP];
    __shared__ int      s_off[CHUNK_CAP];
    __shared__ int      s_wsum[NWB];
    __shared__ int      s_woff[NWB];
    __shared__ int      s_total, s_before, s_gtot, s_start;

    const int tid  = threadIdx.x;
    const int lane = tid & 31;
    const int wid  = tid >> 5;
    const int bid  = blockIdx.x;
    const unsigned FULL = 0xffffffffu;
    const unsigned lt   = (1u << lane) - 1u;

    // ---- Sort phase (fused): one warp per node, grid-strided ----
    if (tid == 0)
        *(volatile unsigned long long*)&g_cnt_tag[bid] = 0ULL;  // per-run reset

    for (int node = bid * NWB + wid; node < N; node += NBLOCKS * NWB) {
        int e = (node << 5) + lane;
        int v = edge_index[E + e];                 // dst row of edge_index [2,E]
        float4 q = reinterpret_cast<const float4*>(edge_attr)[e];

        float err = err_key(q.x);                  // component 0 = w
        unsigned long long key =
            ((unsigned long long)__float_as_uint(err) << 6) | (unsigned)lane;

        #pragma unroll
        for (int k = 2; k <= 32; k <<= 1) {
            #pragma unroll
            for (int j = k >> 1; j > 0; j >>= 1) {
                unsigned long long o = __shfl_xor_sync(FULL, key, j);
                bool lower    = (lane & j) == 0;
                bool asc      = (lane & k) == 0;
                bool keep_min = (lower == asc);
                bool swap     = keep_min ? (o < key) : (o > key);
                if (swap) key = o;
            }
        }

        int o = (int)(key & 63u);
        int    sv = __shfl_sync(FULL, v,   o);
        float4 sq;
        sq.x = __shfl_sync(FULL, q.x, o);
        sq.y = __shfl_sync(FULL, q.y, o);
        sq.z = __shfl_sync(FULL, q.z, o);
        sq.w = __shfl_sync(FULL, q.w, o);

        g_nbr[e]  = sv;
        g_quat[e] = sq;

        if (lane == 0) {
            g_claim[node] = 0xffffffffu;                        // reinit per run
            g_nq[node]    = make_float4(1.f, 0.f, 0.f, 0.f);    // identity
        }
        if (lane < 4)
            out[base + node * 4 + lane] = (lane == 0) ? 1.0f : 0.0f;
    }

    if (tid == 0) {
        int st = start_ptr ? __ldcg(start_ptr) : 0;
        if (st < 0 || st >= N) st = 0;
        s_start = st;
        if (bid == 0) {
            for (int i = 0; i < base; i++) out[i] = (float)st;
            __stcg(&g_queue[0], st);
            __stcg(&g_levels[0], 0);
            __stcg(&g_levels[1], 1);
        }
    }
    __syncthreads();
    const int start = s_start;
    grid_barrier();

    // ---- Level-synchronous BFS ----
    int lev_beg = 0, lev_end = 1, tail = 1, lev = 0;

    while (lev < MAX_LEV) {
        int len = lev_end - lev_beg;
        if (len <= 0) break;
        bool fast = (len <= FAST_MAX);

        int cbeg, clen;
        if (fast) { cbeg = lev_beg; clen = (bid == 0) ? len : 0; }
        else {
            int chunk = (len + NBLOCKS - 1) / NBLOCKS;        // <= CHUNK_CAP
            cbeg = lev_beg + bid * chunk;
            int cend = cbeg + chunk; if (cend > lev_end) cend = lev_end;
            clen = cend - cbeg; if (clen < 0) clen = 0;
        }

        // coop preload of queue chunk (high MLP)
        for (int i = tid; i < clen; i += NTHREADS)
            s_u[i] = __ldcg(&g_queue[cbeg + i]);
        __syncthreads();

        // ---- Phase A: claims (smem u -> nbr -> RED.MIN) ----
        for (int ei = wid; ei < clen; ei += NWB) {
            int u = s_u[ei];
            int v = g_nbr[(u << 5) + lane];
            atomicMin(&g_claim[v], (unsigned)(((cbeg + ei) << 5) | lane));
        }
        if (fast) { if (bid == 0) __syncthreads(); }
        else grid_barrier();

        // ---- Phase B: winner masks (monotone keys => equality suffices) ----
        for (int ei = wid; ei < clen; ei += NWB) {
            int p = cbeg + ei;
            int u = s_u[ei];
            int v = g_nbr[(u << 5) + lane];        // L1 hit
            bool win = (v != start) &&
                       (__ldcg(&g_claim[v]) == (unsigned)((p << 5) | lane));
            unsigned m = __ballot_sync(FULL, win);
            if (lane == 0) s_win[ei] = m;
        }
        if (!fast || bid == 0) {
            __syncthreads();
            int c = (tid < clen) ? __popc(s_win[tid]) : 0;
            int x = c;
            #pragma unroll
            for (int d = 1; d < 32; d <<= 1) {
                int y = __shfl_up_sync(FULL, x, d);
                if (lane >= d) x += y;
            }
            if (lane == 31) s_wsum[wid] = x;
            __syncthreads();
            if (wid == 0 && lane < NWB) {
                int w = s_wsum[lane];
                int xx = w;
                #pragma unroll
                for (int d = 1; d < NWB; d <<= 1) {
                    int y = __shfl_up_sync(0x0000ffffu, xx, d);
                    if (lane >= d) xx += y;
                }
                s_woff[lane] = xx - w;
                if (lane == NWB - 1) s_total = xx;
            }
            __syncthreads();
            if (tid < clen) s_off[tid] = x - c + s_woff[wid];
            __syncthreads();
        }

        int blkoff, gtot;
        unsigned tag = (unsigned)(lev + 1);
        if (fast) {
            blkoff = tail;
            gtot = s_total;                         // only block 0 uses it
        } else {
            // tagged publish + spin-gather (replaces a full grid barrier)
            if (tid == 0)
                *(volatile unsigned long long*)&g_cnt_tag[bid] =
                    (((unsigned long long)tag) << 32) | (unsigned)s_total;
            __syncthreads();
            if (wid == 0) {
                int acc_b = 0, acc_t = 0;
                for (int j = lane; j < NBLOCKS; j += 32) {
                    volatile unsigned long long* p = &g_cnt_tag[j];
                    unsigned long long vv;
                    while (((vv = *p) >> 32) != tag) __nanosleep(20);
                    int cc = (int)(unsigned)vv;
                    acc_t += cc;
                    if (j < bid) acc_b += cc;
                }
                #pragma unroll
                for (int d = 16; d > 0; d >>= 1) {
                    acc_b += __shfl_xor_sync(FULL, acc_b, d);
                    acc_t += __shfl_xor_sync(FULL, acc_t, d);
                }
                if (lane == 0) { s_before = acc_b; s_gtot = acc_t; }
            }
            __syncthreads();
            blkoff = tail + s_before;
            gtot = s_gtot;
        }

        // ---- Phase C: ordered queue writes + quat computation at claim ----
        for (int ei = wid; ei < clen; ei += NWB) {
            unsigned m = s_win[ei];
            if (m == 0u) continue;
            int u    = s_u[ei];
            int eoff = s_off[ei];
            if ((m >> lane) & 1u) {
                int e = (u << 5) + lane;
                int v = g_nbr[e];
                int pos = blkoff + eoff + __popc(m & lt);
                __stcg(&g_queue[pos], v);
                float4 q  = g_quat[e];
                float4 uq = __ldcg(&g_nq[u]);
                // qmul(inv(q), qu):  inv(q) = (w, -x, -y, -z)
                float w1 = q.x, x1 = -q.y, y1 = -q.z, z1 = -q.w;
                float4 r;
                r.x = w1 * uq.x - x1 * uq.y - y1 * uq.z - z1 * uq.w;
                r.y = w1 * uq.y + x1 * uq.x + y1 * uq.w - z1 * uq.z;
                r.z = w1 * uq.z - x1 * uq.w + y1 * uq.x + z1 * uq.y;
                r.w = w1 * uq.w + x1 * uq.z - y1 * uq.y + z1 * uq.x;
                __stcg(&g_nq[v], r);
                __stcg(&out[base + 4 * v + 0], r.x);
                __stcg(&out[base + 4 * v + 1], r.y);
                __stcg(&out[base + 4 * v + 2], r.z);
                __stcg(&out[base + 4 * v + 3], r.w);
            }
        }

        if (bid == 0 && tid == 0)
            __stcg(&g_levels[lev + 2], tail + gtot);
        grid_barrier();

        lev++;
        lev_beg = lev_end;
        lev_end = __ldcg(&g_levels[lev + 1]);
        tail    = lev_end;
    }
}

extern "C" void kernel_launch(void* const* d_in, const int* in_sizes, int n_in,
                              void* d_out, int out_size) {
    const float* edge_attr  = (const float*)d_in[0];
    const int*   edge_index = (const int*)d_in[1];
    const int*   start_ptr  = (n_in >= 3) ? (const int*)d_in[2] : nullptr;
    float* out = (float*)d_out;

    int E = in_sizes[0] / 4;     // edge_attr is [E,4]
    int N = E / DEG;
    if (N > N_MAX) N = N_MAX;
    int base = out_size - N * 4;
    if (base < 0) base = 0;

    spt_kernel<<<NBLOCKS, NTHREADS>>>(edge_attr, edge_index, start_ptr, out, N, E, base);
}

// round 6
// speedup vs baseline: 70.6333x; 1.0632x over previous
#include <cuda_runtime.h>
#include <stdint.h>

#define N_MAX     20000
#define DEG       32
#define NBLOCKS   112
#define NTHREADS  512
#define NWB       (NTHREADS / 32)      // 16 warps per block
#define CHUNK_CAP 192                  // >= ceil(N_MAX/NBLOCKS)=179, >= FAST_MAX
#define FAST_MAX  128                  // small-level single-block fast path
#define MAX_LEV   60

// Scratch (static __device__ — no allocations allowed)
__device__ unsigned g_packed[N_MAX * DEG];   // (v<<5)|rank per edge (orig layout)
__device__ float4   g_nq[N_MAX];             // node quaternions
__device__ unsigned g_claim[N_MAX];          // min claim key (reinit per run)
__device__ unsigned g_queue[N_MAX];          // tagged queue: (lev+1)<<16 | v
__device__ unsigned g_slotA[NBLOCKS];        // per-block claim-done tag (monotone)
__device__ unsigned long long g_cnt[MAX_LEV + 2][NBLOCKS];  // per-level counts
__device__ unsigned long long g_ctrl;        // fast->big / DONE control word

// single-use hierarchical grid barrier (monotone counters; replay-safe)
__device__ unsigned          g_bar_sub[4];
__device__ unsigned          g_bar_root;
__device__ volatile unsigned g_bar_gen;

__device__ __forceinline__ void grid_barrier() {
    __syncthreads();
    if (threadIdx.x == 0) {
        unsigned gen = g_bar_gen;
        __threadfence();
        int s = blockIdx.x & 3;
        unsigned my = atomicAdd(&g_bar_sub[s], 1u) + 1u;
        if ((my % (NBLOCKS / 4)) == 0u) {
            unsigned r = atomicAdd(&g_bar_root, 1u) + 1u;
            if ((r & 3u) == 0u) { __threadfence(); g_bar_gen = gen + 1u; }
        }
        while (g_bar_gen == gen) __nanosleep(20);
        __threadfence();
    }
    __syncthreads();
}

// release/acquire helpers (gpu scope)
__device__ __forceinline__ unsigned ld_acq32(const unsigned* p) {
    unsigned v;
    asm volatile("ld.global.acquire.gpu.b32 %0, [%1];" : "=r"(v) : "l"(p) : "memory");
    return v;
}
__device__ __forceinline__ void st_rel32(unsigned* p, unsigned v) {
    asm volatile("st.global.release.gpu.b32 [%0], %1;" :: "l"(p), "r"(v) : "memory");
}
__device__ __forceinline__ unsigned long long ld_acq64(const unsigned long long* p) {
    unsigned long long v;
    asm volatile("ld.global.acquire.gpu.b64 %0, [%1];" : "=l"(v) : "l"(p) : "memory");
    return v;
}
__device__ __forceinline__ void st_rel64(unsigned long long* p, unsigned long long v) {
    asm volatile("st.global.release.gpu.b64 [%0], %1;" :: "l"(p), "l"(v) : "memory");
}

// Replicate XLA's acos lowering: acos(x)=2*atan2(sqrt(1-x*x),1+x), all f32 RN.
__device__ __forceinline__ float err_key(float w) {
    float x = fminf(fabsf(w), 1.0f);
    float t = __fsub_rn(1.0f, __fmul_rn(x, x));
    float s = __fsqrt_rn(t);
    float a = atan2f(s, __fadd_rn(1.0f, x));
    float acosv = __fmul_rn(2.0f, a);
    float deg   = __fmul_rn(acosv, 57.29577951308232f);
    return __fmul_rn(2.0f, deg);
}

struct Smem {
    int      s_u[CHUNK_CAP];
    unsigned s_winl[CHUNK_CAP];
    unsigned s_winr[CHUNK_CAP];
    int      s_off[CHUNK_CAP];
    int      s_wsum[NWB];
    int      s_woff[NWB];
    int      s_total, s_before, s_gtot, s_start;
    unsigned long long s_ctrl;
};

// Process one BFS level. Exact reference order: node v claimed by min key
// (queue_pos<<5 | rank); next-level queue = ascending winner key.
// big=true: all blocks (chunked, slotA tag barrier + per-level count gather).
// big=false: block 0 alone (__syncthreads only).
__device__ __forceinline__ int process_level(
    Smem& sm, const float4* __restrict__ ea4, float* __restrict__ out, int base,
    int lev, int beg, int end, int start, bool big)
{
    const int tid = threadIdx.x, lane = tid & 31, wid = tid >> 5, bid = blockIdx.x;
    const unsigned FULL = 0xffffffffu;
    const int len = end - beg;
    int cbeg, clen;
    if (big) {
        int chunk = (len + NBLOCKS - 1) / NBLOCKS;         // <= CHUNK_CAP
        cbeg = beg + bid * chunk;
        int cend = cbeg + chunk; if (cend > end) cend = end;
        clen = cend - cbeg; if (clen < 0) clen = 0;
    } else { cbeg = beg; clen = len; }
    const unsigned tag = (unsigned)(lev + 1);

    // acquire-spin queue entries (overlaps stragglers' Phase C of prior level)
    for (int i = tid; i < clen; i += NTHREADS) {
        unsigned qv;
        for (;;) {
            qv = ld_acq32(&g_queue[cbeg + i]);
            if ((qv >> 16) == tag) break;
            __nanosleep(20);
        }
        sm.s_u[i] = (int)(qv & 0xffffu);
    }
    __syncthreads();

    // Phase A: claims
    for (int ei = wid; ei < clen; ei += NWB) {
        unsigned pk = g_packed[(sm.s_u[ei] << 5) + lane];
        atomicMin(&g_claim[pk >> 5], (((unsigned)(cbeg + ei)) << 5) | (pk & 31u));
    }
    __syncthreads();
    if (big) {
        if (tid == 0) st_rel32(&g_slotA[bid], tag);
        if (wid == 0)
            for (int j = lane; j < NBLOCKS; j += 32)
                while (ld_acq32(&g_slotA[j]) < tag) __nanosleep(20);
        __syncthreads();
    }

    // Phase B: winner masks (lane mask + rank mask)
    for (int ei = wid; ei < clen; ei += NWB) {
        unsigned pk = g_packed[(sm.s_u[ei] << 5) + lane];   // L1 hit
        int v = (int)(pk >> 5); unsigned rk = pk & 31u;
        bool win = (v != start) &&
                   (__ldcg(&g_claim[v]) == ((((unsigned)(cbeg + ei)) << 5) | rk));
        unsigned lm = __ballot_sync(FULL, win);
        unsigned rm = win ? (1u << rk) : 0u;
        #pragma unroll
        for (int d = 16; d; d >>= 1) rm |= __shfl_xor_sync(FULL, rm, d);
        if (lane == 0) { sm.s_winl[ei] = lm; sm.s_winr[ei] = rm; }
    }
    __syncthreads();

    // exclusive scan of winner counts over the chunk
    int c = (tid < clen) ? __popc(sm.s_winl[tid]) : 0;
    int x = c;
    #pragma unroll
    for (int d = 1; d < 32; d <<= 1) {
        int y = __shfl_up_sync(FULL, x, d);
        if (lane >= d) x += y;
    }
    if (lane == 31) sm.s_wsum[wid] = x;
    __syncthreads();
    if (wid == 0 && lane < NWB) {
        int w = sm.s_wsum[lane], xx = w;
        #pragma unroll
        for (int d = 1; d < NWB; d <<= 1) {
            int y = __shfl_up_sync(0x0000ffffu, xx, d);
            if (lane >= d) xx += y;
        }
        sm.s_woff[lane] = xx - w;
        if (lane == NWB - 1) sm.s_total = xx;
    }
    __syncthreads();
    if (tid < clen) sm.s_off[tid] = x - c + sm.s_woff[wid];
    __syncthreads();

    int blkoff, gtot;
    if (big) {
        if (tid == 0)
            st_rel64(&g_cnt[lev][bid],
                     (((unsigned long long)tag) << 32) | (unsigned)sm.s_total);
        if (wid == 0) {
            int accb = 0, acct = 0;
            for (int j = lane; j < NBLOCKS; j += 32) {
                unsigned long long vv;
                for (;;) {
                    vv = ld_acq64(&g_cnt[lev][j]);
                    if ((unsigned)(vv >> 32) == tag) break;
                    __nanosleep(20);
                }
                int cc = (int)(vv & 0xffffffffu);
                acct += cc; if (j < bid) accb += cc;
            }
            #pragma unroll
            for (int d = 16; d; d >>= 1) {
                accb += __shfl_xor_sync(FULL, accb, d);
                acct += __shfl_xor_sync(FULL, acct, d);
            }
            if (lane == 0) { sm.s_before = accb; sm.s_gtot = acct; }
        }
        __syncthreads();
        blkoff = end + sm.s_before;
        gtot   = sm.s_gtot;
    } else {
        blkoff = end;
        gtot   = sm.s_total;
    }

    // Phase C: quat at claim time; release-tagged queue write (no barrier after)
    for (int ei = wid; ei < clen; ei += NWB) {
        unsigned lm = sm.s_winl[ei];
        if (!lm) continue;
        if ((lm >> lane) & 1u) {
            int u = sm.s_u[ei];
            int e = (u << 5) + lane;
            unsigned pk = g_packed[e];
            int v = (int)(pk >> 5); unsigned rk = pk & 31u;
            unsigned rm = sm.s_winr[ei];
            int pos = blkoff + sm.s_off[ei] + __popc(rm & ((1u << rk) - 1u));
            float4 q  = ea4[e];
            float4 uq = __ldcg(&g_nq[u]);
            // qmul(inv(q), qu):  inv(q) = (w, -x, -y, -z)
            float w1 = q.x, x1 = -q.y, y1 = -q.z, z1 = -q.w;
            float4 r;
            r.x = w1*uq.x - x1*uq.y - y1*uq.z - z1*uq.w;
            r.y = w1*uq.y + x1*uq.x + y1*uq.w - z1*uq.z;
            r.z = w1*uq.z - x1*uq.w + y1*uq.x + z1*uq.y;
            r.w = w1*uq.w + x1*uq.z - y1*uq.y + z1*uq.x;
            __stcg(&g_nq[v], r);
            __stcg(&out[base + 4*v + 0], r.x);
            __stcg(&out[base + 4*v + 1], r.y);
            __stcg(&out[base + 4*v + 2], r.z);
            __stcg(&out[base + 4*v + 3], r.w);
            st_rel32(&g_queue[pos], ((tag + 1u) << 16) | (unsigned)v);
        }
    }
    __syncthreads();   // s_* reuse safety for next level
    return gtot;
}

__global__ __launch_bounds__(NTHREADS, 1)
void spt_kernel(const float* __restrict__ edge_attr,
                const int*   __restrict__ edge_index,
                const int*   __restrict__ start_ptr,
                float* __restrict__ out, int N, int E, int base) {
    __shared__ Smem sm;
    const int tid = threadIdx.x, lane = tid & 31, wid = tid >> 5, bid = blockIdx.x;
    const unsigned FULL = 0xffffffffu;

    if (tid == 0) {
        int s = start_ptr ? __ldcg(start_ptr) : 0;
        if (s < 0 || s >= N) s = 0;
        sm.s_start = s;
    }
    __syncthreads();
    const int start = sm.s_start;

    // ---- per-run resets (pre-barrier) ----
    if (tid == 0) {
        g_slotA[bid] = 0u;
        if (bid == 0) {
            g_ctrl = 0ULL;
            g_nq[start] = make_float4(1.f, 0.f, 0.f, 0.f);
            for (int i = 0; i < base; i++) out[i] = (float)start;
        }
    }
    for (int l = tid; l < MAX_LEV + 2; l += NTHREADS) g_cnt[l][bid] = 0ULL;

    for (int i = bid * NTHREADS + tid; i < N; i += NBLOCKS * NTHREADS) {
        g_claim[i] = 0xffffffffu;
        g_queue[i] = (i == 0) ? ((1u << 16) | (unsigned)start) : 0u;
        out[base + 4*i + 0] = 1.f;
        out[base + 4*i + 1] = 0.f;
        out[base + 4*i + 2] = 0.f;
        out[base + 4*i + 3] = 0.f;
    }

    // ---- rank phase: stable rank of each edge within its node (no sort copy) ----
    for (int node = bid * NWB + wid; node < N; node += NBLOCKS * NWB) {
        int e = (node << 5) + lane;
        int v = edge_index[E + e];             // dst row of edge_index [2,E]
        float err = err_key(edge_attr[4 * e]); // component 0 = w
        unsigned kb = __float_as_uint(err);    // err>=0: bits order-preserving
        int rk = 0;
        #pragma unroll
        for (int j = 0; j < 32; j++) {
            unsigned kj = __shfl_sync(FULL, kb, j);
            rk += (kj < kb) || (kj == kb && j < lane);
        }
        g_packed[e] = (((unsigned)v) << 5) | (unsigned)rk;
    }

    grid_barrier();

    // ---- level-synchronous BFS ----
    const float4* ea4 = reinterpret_cast<const float4*>(edge_attr);
    int lev = 0, beg = 0, end = 1;
    unsigned long long last_ctrl = 0ULL;
    bool prev_big = false;

    while (true) {
        int len = end - beg;
        if (len <= 0 || lev >= MAX_LEV) {
            if (bid == 0 && tid == 0)
                st_rel64(&g_ctrl, (1ULL << 63) |
                                  (((unsigned long long)(lev + 1)) << 32));
            return;
        }
        bool fast = (len <= FAST_MAX);
        if (fast && bid != 0) {
            // sleep until block 0 publishes the next big level (or DONE)
            if (tid == 0) {
                unsigned long long cw;
                for (;;) {
                    cw = ld_acq64(&g_ctrl);
                    if (cw != last_ctrl) break;
                    __nanosleep(60);
                }
                sm.s_ctrl = cw;
            }
            __syncthreads();
            unsigned long long cw = sm.s_ctrl;
            last_ctrl = cw;
            if (cw >> 63) return;
            lev = (int)((cw >> 32) & 0xffffu) - 1;
            beg = (int)((cw >> 16) & 0xffffu);
            end = (int)(cw & 0xffffu);
            int gtot = process_level(sm, ea4, out, base, lev, beg, end, start, true);
            prev_big = true;
            beg = end; end += gtot; lev++;
            continue;
        }
        if (!fast && !prev_big && bid == 0 && tid == 0)
            st_rel64(&g_ctrl, (((unsigned long long)(lev + 1)) << 32) |
                              (((unsigned long long)beg) << 16) | (unsigned)end);
        int gtot = process_level(sm, ea4, out, base, lev, beg, end, start, !fast);
        prev_big = !fast;
        beg = end; end += gtot; lev++;
    }
}

extern "C" void kernel_launch(void* const* d_in, const int* in_sizes, int n_in,
                              void* d_out, int out_size) {
    const float* edge_attr  = (const float*)d_in[0];
    const int*   edge_index = (const int*)d_in[1];
    const int*   start_ptr  = (n_in >= 3) ? (const int*)d_in[2] : nullptr;
    float* out = (float*)d_out;

    int E = in_sizes[0] / 4;     // edge_attr is [E,4]
    int N = E / DEG;
    if (N > N_MAX) N = N_MAX;
    int base = out_size - N * 4;
    if (base < 0) base = 0;

    spt_kernel<<<NBLOCKS, NTHREADS>>>(edge_attr, edge_index, start_ptr, out, N, E, base);
}

// round 7
// speedup vs baseline: 77.7533x; 1.1008x over previous
#include <cuda_runtime.h>
#include <stdint.h>

#define N_MAX     20000
#define DEG       32
#define NBLOCKS   112
#define NTHREADS  512
#define NWB       (NTHREADS / 32)      // 16 warps per block
#define CHUNK_CAP 192                  // >= ceil(N_MAX/NBLOCKS)=179, >= FAST_MAX
#define FAST_MAX  128                  // small-level single-block fast path
#define MAX_LEV   60

// Scratch (static __device__ — no allocations allowed)
__device__ unsigned g_packed[N_MAX * DEG];   // (v<<5)|rank per edge (orig layout)
__device__ float4   g_nq[N_MAX];             // node quaternions
__device__ unsigned g_claim[N_MAX];          // min claim key (reinit per run)
__device__ unsigned g_queue[N_MAX];          // tagged queue: (lev+1)<<16 | v
__device__ unsigned g_slotA[NBLOCKS];        // per-block claim-done tag (monotone)
__device__ unsigned long long g_cnt[MAX_LEV + 2][NBLOCKS];  // per-level counts
__device__ unsigned long long g_ctrl;        // fast->big / DONE control word

// single-use hierarchical grid barrier (monotone counters; replay-safe)
__device__ unsigned          g_bar_sub[4];
__device__ unsigned          g_bar_root;
__device__ volatile unsigned g_bar_gen;

__device__ __forceinline__ void grid_barrier() {
    __syncthreads();
    if (threadIdx.x == 0) {
        unsigned gen = g_bar_gen;
        __threadfence();
        int s = blockIdx.x & 3;
        unsigned my = atomicAdd(&g_bar_sub[s], 1u) + 1u;
        if ((my % (NBLOCKS / 4)) == 0u) {
            unsigned r = atomicAdd(&g_bar_root, 1u) + 1u;
            if ((r & 3u) == 0u) { __threadfence(); g_bar_gen = gen + 1u; }
        }
        while (g_bar_gen == gen) __nanosleep(20);
        __threadfence();
    }
    __syncthreads();
}

// release/acquire helpers (gpu scope)
__device__ __forceinline__ unsigned ld_acq32(const unsigned* p) {
    unsigned v;
    asm volatile("ld.global.acquire.gpu.b32 %0, [%1];" : "=r"(v) : "l"(p) : "memory");
    return v;
}
__device__ __forceinline__ void st_rel32(unsigned* p, unsigned v) {
    asm volatile("st.global.release.gpu.b32 [%0], %1;" :: "l"(p), "r"(v) : "memory");
}
__device__ __forceinline__ unsigned long long ld_acq64(const unsigned long long* p) {
    unsigned long long v;
    asm volatile("ld.global.acquire.gpu.b64 %0, [%1];" : "=l"(v) : "l"(p) : "memory");
    return v;
}
__device__ __forceinline__ void st_rel64(unsigned long long* p, unsigned long long v) {
    asm volatile("st.global.release.gpu.b64 [%0], %1;" :: "l"(p), "l"(v) : "memory");
}

// Replicate XLA's acos lowering: acos(x)=2*atan2(sqrt(1-x*x),1+x), all f32 RN.
__device__ __forceinline__ float err_key(float w) {
    float x = fminf(fabsf(w), 1.0f);
    float t = __fsub_rn(1.0f, __fmul_rn(x, x));
    float s = __fsqrt_rn(t);
    float a = atan2f(s, __fadd_rn(1.0f, x));
    float acosv = __fmul_rn(2.0f, a);
    float deg   = __fmul_rn(acosv, 57.29577951308232f);
    return __fmul_rn(2.0f, deg);
}

struct Smem {
    int      s_u[CHUNK_CAP];
    unsigned s_winl[CHUNK_CAP];
    unsigned s_winr[CHUNK_CAP];
    int      s_off[CHUNK_CAP];
    int      s_wsum[NWB];
    int      s_woff[NWB];
    int      s_total, s_before, s_gtot, s_start;
    unsigned long long s_ctrl;
};

// Process one BFS level. Exact reference order: node v claimed by min key
// (queue_pos<<5 | rank); next-level queue = ascending winner key.
// big=true: all blocks (chunked, slotA tag barrier + per-level count gather).
// big=false: block 0 alone (__syncthreads only).
__device__ __forceinline__ int process_level(
    Smem& sm, const float4* __restrict__ ea4, float* __restrict__ out, int base,
    int lev, int beg, int end, int start, bool big)
{
    const int tid = threadIdx.x, lane = tid & 31, wid = tid >> 5, bid = blockIdx.x;
    const unsigned FULL = 0xffffffffu;
    const int len = end - beg;
    int cbeg, clen;
    if (big) {
        int chunk = (len + NBLOCKS - 1) / NBLOCKS;         // <= CHUNK_CAP
        cbeg = beg + bid * chunk;
        int cend = cbeg + chunk; if (cend > end) cend = end;
        clen = cend - cbeg; if (clen < 0) clen = 0;
    } else { cbeg = beg; clen = len; }
    const unsigned tag = (unsigned)(lev + 1);

    // acquire-spin queue entries (overlaps stragglers' Phase C of prior level)
    for (int i = tid; i < clen; i += NTHREADS) {
        unsigned qv;
        for (;;) {
            qv = ld_acq32(&g_queue[cbeg + i]);
            if ((qv >> 16) == tag) break;
            __nanosleep(20);
        }
        sm.s_u[i] = (int)(qv & 0xffffu);
    }
    __syncthreads();

    // Phase A: claims
    for (int ei = wid; ei < clen; ei += NWB) {
        unsigned pk = g_packed[(sm.s_u[ei] << 5) + lane];
        atomicMin(&g_claim[pk >> 5], (((unsigned)(cbeg + ei)) << 5) | (pk & 31u));
    }
    __syncthreads();
    if (big) {
        if (tid == 0) st_rel32(&g_slotA[bid], tag);
        if (wid == 0)
            for (int j = lane; j < NBLOCKS; j += 32)
                while (ld_acq32(&g_slotA[j]) < tag) __nanosleep(20);
        __syncthreads();
    }

    // Phase B: winner masks (lane mask + rank mask)
    for (int ei = wid; ei < clen; ei += NWB) {
        unsigned pk = g_packed[(sm.s_u[ei] << 5) + lane];   // L1 hit
        int v = (int)(pk >> 5); unsigned rk = pk & 31u;
        bool win = (v != start) &&
                   (__ldcg(&g_claim[v]) == ((((unsigned)(cbeg + ei)) << 5) | rk));
        unsigned lm = __ballot_sync(FULL, win);
        unsigned rm = win ? (1u << rk) : 0u;
        #pragma unroll
        for (int d = 16; d; d >>= 1) rm |= __shfl_xor_sync(FULL, rm, d);
        if (lane == 0) { sm.s_winl[ei] = lm; sm.s_winr[ei] = rm; }
    }
    __syncthreads();

    // exclusive scan of winner counts over the chunk
    int c = (tid < clen) ? __popc(sm.s_winl[tid]) : 0;
    int x = c;
    #pragma unroll
    for (int d = 1; d < 32; d <<= 1) {
        int y = __shfl_up_sync(FULL, x, d);
        if (lane >= d) x += y;
    }
    if (lane == 31) sm.s_wsum[wid] = x;
    __syncthreads();
    if (wid == 0 && lane < NWB) {
        int w = sm.s_wsum[lane], xx = w;
        #pragma unroll
        for (int d = 1; d < NWB; d <<= 1) {
            int y = __shfl_up_sync(0x0000ffffu, xx, d);
            if (lane >= d) xx += y;
        }
        sm.s_woff[lane] = xx - w;
        if (lane == NWB - 1) sm.s_total = xx;
    }
    __syncthreads();
    if (tid < clen) sm.s_off[tid] = x - c + sm.s_woff[wid];
    __syncthreads();

    int blkoff, gtot;
    if (big) {
        if (tid == 0)
            st_rel64(&g_cnt[lev][bid],
                     (((unsigned long long)tag) << 32) | (unsigned)sm.s_total);
        if (wid == 0) {
            int accb = 0, acct = 0;
            for (int j = lane; j < NBLOCKS; j += 32) {
                unsigned long long vv;
                for (;;) {
                    vv = ld_acq64(&g_cnt[lev][j]);
                    if ((unsigned)(vv >> 32) == tag) break;
                    __nanosleep(20);
                }
                int cc = (int)(vv & 0xffffffffu);
                acct += cc; if (j < bid) accb += cc;
            }
            #pragma unroll
            for (int d = 16; d; d >>= 1) {
                accb += __shfl_xor_sync(FULL, accb, d);
                acct += __shfl_xor_sync(FULL, acct, d);
            }
            if (lane == 0) { sm.s_before = accb; sm.s_gtot = acct; }
        }
        __syncthreads();
        blkoff = end + sm.s_before;
        gtot   = sm.s_gtot;
    } else {
        blkoff = end;
        gtot   = sm.s_total;
    }

    // Phase C: quat at claim time; release-tagged queue write (no barrier after)
    for (int ei = wid; ei < clen; ei += NWB) {
        unsigned lm = sm.s_winl[ei];
        if (!lm) continue;
        if ((lm >> lane) & 1u) {
            int u = sm.s_u[ei];
            int e = (u << 5) + lane;
            unsigned pk = g_packed[e];
            int v = (int)(pk >> 5); unsigned rk = pk & 31u;
            unsigned rm = sm.s_winr[ei];
            int pos = blkoff + sm.s_off[ei] + __popc(rm & ((1u << rk) - 1u));
            float4 q  = ea4[e];
            float4 uq = __ldcg(&g_nq[u]);
            // qmul(inv(q), qu):  inv(q) = (w, -x, -y, -z)
            float w1 = q.x, x1 = -q.y, y1 = -q.z, z1 = -q.w;
            float4 r;
            r.x = w1*uq.x - x1*uq.y - y1*uq.z - z1*uq.w;
            r.y = w1*uq.y + x1*uq.x + y1*uq.w - z1*uq.z;
            r.z = w1*uq.z - x1*uq.w + y1*uq.x + z1*uq.y;
            r.w = w1*uq.w + x1*uq.z - y1*uq.y + z1*uq.x;
            __stcg(&g_nq[v], r);
            __stcg(&out[base + 4*v + 0], r.x);
            __stcg(&out[base + 4*v + 1], r.y);
            __stcg(&out[base + 4*v + 2], r.z);
            __stcg(&out[base + 4*v + 3], r.w);
            st_rel32(&g_queue[pos], ((tag + 1u) << 16) | (unsigned)v);
        }
    }
    __syncthreads();   // s_* reuse safety for next level
    return gtot;
}

__global__ __launch_bounds__(NTHREADS, 1)
void spt_kernel(const float* __restrict__ edge_attr,
                const int*   __restrict__ edge_index,
                const int*   __restrict__ start_ptr,
                float* __restrict__ out, int N, int E, int base) {
    __shared__ Smem sm;
    const int tid = threadIdx.x, lane = tid & 31, wid = tid >> 5, bid = blockIdx.x;
    const unsigned FULL = 0xffffffffu;

    if (tid == 0) {
        int s = start_ptr ? __ldcg(start_ptr) : 0;
        if (s < 0 || s >= N) s = 0;
        sm.s_start = s;
    }
    __syncthreads();
    const int start = sm.s_start;

    // ---- per-run resets (pre-barrier) ----
    if (tid == 0) {
        g_slotA[bid] = 0u;
        if (bid == 0) {
            g_ctrl = 0ULL;
            g_nq[start] = make_float4(1.f, 0.f, 0.f, 0.f);
            for (int i = 0; i < base; i++) out[i] = (float)start;
        }
    }
    for (int l = tid; l < MAX_LEV + 2; l += NTHREADS) g_cnt[l][bid] = 0ULL;

    for (int i = bid * NTHREADS + tid; i < N; i += NBLOCKS * NTHREADS) {
        g_claim[i] = 0xffffffffu;
        g_queue[i] = (i == 0) ? ((1u << 16) | (unsigned)start) : 0u;
        out[base + 4*i + 0] = 1.f;
        out[base + 4*i + 1] = 0.f;
        out[base + 4*i + 2] = 0.f;
        out[base + 4*i + 3] = 0.f;
    }

    // ---- rank phase: stable rank of each edge within its node (no sort copy) ----
    for (int node = bid * NWB + wid; node < N; node += NBLOCKS * NWB) {
        int e = (node << 5) + lane;
        int v = edge_index[E + e];             // dst row of edge_index [2,E]
        float err = err_key(edge_attr[4 * e]); // component 0 = w
        unsigned kb = __float_as_uint(err);    // err>=0: bits order-preserving
        int rk = 0;
        #pragma unroll
        for (int j = 0; j < 32; j++) {
            unsigned kj = __shfl_sync(FULL, kb, j);
            rk += (kj < kb) || (kj == kb && j < lane);
        }
        g_packed[e] = (((unsigned)v) << 5) | (unsigned)rk;
    }

    grid_barrier();

    // ---- level-synchronous BFS ----
    const float4* ea4 = reinterpret_cast<const float4*>(edge_attr);
    int lev = 0, beg = 0, end = 1;
    unsigned long long last_ctrl = 0ULL;
    bool prev_big = false;

    while (true) {
        int len = end - beg;
        if (len <= 0 || lev >= MAX_LEV) {
            if (bid == 0 && tid == 0)
                st_rel64(&g_ctrl, (1ULL << 63) |
                                  (((unsigned long long)(lev + 1)) << 32));
            return;
        }
        bool fast = (len <= FAST_MAX);
        if (fast && bid != 0) {
            // sleep until block 0 publishes the next big level (or DONE)
            if (tid == 0) {
                unsigned long long cw;
                for (;;) {
                    cw = ld_acq64(&g_ctrl);
                    if (cw != last_ctrl) break;
                    __nanosleep(60);
                }
                sm.s_ctrl = cw;
            }
            __syncthreads();
            unsigned long long cw = sm.s_ctrl;
            last_ctrl = cw;
            if (cw >> 63) return;
            lev = (int)((cw >> 32) & 0xffffu) - 1;
            beg = (int)((cw >> 16) & 0xffffu);
            end = (int)(cw & 0xffffu);
            int gtot = process_level(sm, ea4, out, base, lev, beg, end, start, true);
            prev_big = true;
            beg = end; end += gtot; lev++;
            continue;
        }
        if (!fast && !prev_big && bid == 0 && tid == 0)
            st_rel64(&g_ctrl, (((unsigned long long)(lev + 1)) << 32) |
                              (((unsigned long long)beg) << 16) | (unsigned)end);
        int gtot = process_level(sm, ea4, out, base, lev, beg, end, start, !fast);
        prev_big = !fast;
        beg = end; end += gtot; lev++;
    }
}

extern "C" void kernel_launch(void* const* d_in, const int* in_sizes, int n_in,
                              void* d_out, int out_size) {
    const float* edge_attr  = (const float*)d_in[0];
    const int*   edge_index = (const int*)d_in[1];
    const int*   start_ptr  = (n_in >= 3) ? (const int*)d_in[2] : nullptr;
    float* out = (float*)d_out;

    int E = in_sizes[0] / 4;     // edge_attr is [E,4]
    int N = E / DEG;
    if (N > N_MAX) N = N_MAX;
    int base = out_size - N * 4;
    if (base < 0) base = 0;

    spt_kernel<<<NBLOCKS, NTHREADS>>>(edge_attr, edge_index, start_ptr, out, N, E, base);
}